// round 2
// baseline (speedup 1.0000x reference)
#include <cuda_runtime.h>
#include <math.h>

#define NROWS 8192
#define DDIM  256
#define MARGIN 0.3f

#define BM 128
#define BN 128
#define BK 16
#define TM 8
#define TN 8
#define LDS_STRIDE 132   // 132 floats = 528 B; 528 % 16 == 0 -> aligned float4 rows

// Scratch (device globals: no allocation allowed in kernel_launch)
__device__ float        g_sq[NROWS];
__device__ unsigned int g_ap[NROWS];   // float bits, running max (dist >= 0 so uint order == float order)
__device__ unsigned int g_an[NROWS];   // float bits, running min
__device__ int          g_tgt[NROWS];  // canonicalized int32 targets
__device__ int          g_is32;        // 1 if targets buffer is int32, 0 if int64

// ---------------------------------------------------------------------------
// Kernel -1: clear dtype-detection flag
// ---------------------------------------------------------------------------
__global__ void init_kernel() { g_is32 = 0; }

// ---------------------------------------------------------------------------
// Kernel 0: row squared norms + re-init of reduction arrays + dtype detection
// Detection: view targets as int32. If the buffer is int64 (values 0..127,
// little-endian), every odd 32-bit word is 0. If int32, the odd words among
// the first 4096 are ~random targets (P(all zero) = 128^-2048 ~= 0).
// Only the first 4096 words are inspected: in-bounds for BOTH dtypes.
// ---------------------------------------------------------------------------
__global__ void prep_kernel(const float* __restrict__ x, const int* __restrict__ t32)
{
    int row  = blockIdx.x * 8 + (threadIdx.x >> 5);   // 8 warps / block
    int lane = threadIdx.x & 31;
    const float* xr = x + (size_t)row * DDIM;
    float s = 0.f;
#pragma unroll
    for (int k = lane; k < DDIM; k += 32) {
        float v = xr[k];
        s = fmaf(v, v, s);
    }
#pragma unroll
    for (int o = 16; o; o >>= 1) s += __shfl_xor_sync(0xffffffffu, s, o);
    if (lane == 0) {
        g_sq[row] = s;
        g_ap[row] = 0u;           // 0.0f
        g_an[row] = 0x7f800000u;  // +inf
        if (row < 2048) {
            if (t32[2 * row + 1] != 0) atomicOr(&g_is32, 1);
        }
    }
}

// ---------------------------------------------------------------------------
// Kernel 0.5: canonicalize targets to int32 in g_tgt
// ---------------------------------------------------------------------------
__global__ void convert_kernel(const void* __restrict__ tgt)
{
    int i = blockIdx.x * 256 + threadIdx.x;
    if (i < NROWS) {
        if (g_is32) g_tgt[i] = ((const int*)tgt)[i];
        else        g_tgt[i] = (int)((const long long*)tgt)[i];
    }
}

// ---------------------------------------------------------------------------
// Kernel 1: fused tile GEMM (X @ X^T) + dist + masked row max/min reduction
// ---------------------------------------------------------------------------
__global__ __launch_bounds__(256, 2)
void tile_kernel(const float* __restrict__ x)
{
    __shared__ float As[BK][LDS_STRIDE];
    __shared__ float Bs[BK][LDS_STRIDE];
    __shared__ float sqA[BM];
    __shared__ float sqB[BN];
    __shared__ int   tA[BM];
    __shared__ int   tB[BN];

    const int r0  = blockIdx.y * BM;
    const int c0  = blockIdx.x * BN;
    const int tid = threadIdx.x;
    const int tx  = tid & 15;
    const int ty  = tid >> 4;

    if (tid < 128) {
        sqA[tid] = g_sq[r0 + tid];
        tA[tid]  = g_tgt[r0 + tid];
    } else {
        int t = tid - 128;
        sqB[t] = g_sq[c0 + t];
        tB[t]  = g_tgt[c0 + t];
    }

    // Global-load mapping: each thread loads 2 float4 per tile (A and B each)
    const int lrow = tid >> 2;          // 0..63
    const int lcol = (tid & 3) * 4;     // 0,4,8,12

    const float* Abase = x + (size_t)(r0 + lrow) * DDIM + lcol;
    const float* Bbase = x + (size_t)(c0 + lrow) * DDIM + lcol;

    float acc[TM][TN];
#pragma unroll
    for (int i = 0; i < TM; i++)
#pragma unroll
        for (int j = 0; j < TN; j++) acc[i][j] = 0.f;

    // prefetch first K-chunk
    float4 a0 = *(const float4*)(Abase);
    float4 a1 = *(const float4*)(Abase + (size_t)64 * DDIM);
    float4 b0 = *(const float4*)(Bbase);
    float4 b1 = *(const float4*)(Bbase + (size_t)64 * DDIM);

    const int NITER = DDIM / BK;
#pragma unroll 1
    for (int kk = 0; kk < NITER; ++kk) {
        As[lcol + 0][lrow]      = a0.x;
        As[lcol + 1][lrow]      = a0.y;
        As[lcol + 2][lrow]      = a0.z;
        As[lcol + 3][lrow]      = a0.w;
        As[lcol + 0][lrow + 64] = a1.x;
        As[lcol + 1][lrow + 64] = a1.y;
        As[lcol + 2][lrow + 64] = a1.z;
        As[lcol + 3][lrow + 64] = a1.w;
        Bs[lcol + 0][lrow]      = b0.x;
        Bs[lcol + 1][lrow]      = b0.y;
        Bs[lcol + 2][lrow]      = b0.z;
        Bs[lcol + 3][lrow]      = b0.w;
        Bs[lcol + 0][lrow + 64] = b1.x;
        Bs[lcol + 1][lrow + 64] = b1.y;
        Bs[lcol + 2][lrow + 64] = b1.z;
        Bs[lcol + 3][lrow + 64] = b1.w;
        __syncthreads();

        if (kk + 1 < NITER) {
            int off = (kk + 1) * BK;
            a0 = *(const float4*)(Abase + off);
            a1 = *(const float4*)(Abase + (size_t)64 * DDIM + off);
            b0 = *(const float4*)(Bbase + off);
            b1 = *(const float4*)(Bbase + (size_t)64 * DDIM + off);
        }

#pragma unroll
        for (int k = 0; k < BK; k++) {
            float4 ra0 = *(const float4*)&As[k][ty * 8];
            float4 ra1 = *(const float4*)&As[k][ty * 8 + 4];
            float4 rb0 = *(const float4*)&Bs[k][tx * 8];
            float4 rb1 = *(const float4*)&Bs[k][tx * 8 + 4];
            float ar[TM] = {ra0.x, ra0.y, ra0.z, ra0.w, ra1.x, ra1.y, ra1.z, ra1.w};
            float br[TN] = {rb0.x, rb0.y, rb0.z, rb0.w, rb1.x, rb1.y, rb1.z, rb1.w};
#pragma unroll
            for (int i = 0; i < TM; i++)
#pragma unroll
                for (int j = 0; j < TN; j++)
                    acc[i][j] = fmaf(ar[i], br[j], acc[i][j]);
        }
        __syncthreads();
    }

    // ---- epilogue: dist + masked max/min, reduce across tx, one atomic/row ----
#pragma unroll
    for (int i = 0; i < TM; i++) {
        const int r    = ty * 8 + i;
        const float sqr = sqA[r];
        const int   tr  = tA[r];
        float ap = 0.f;
        float an = INFINITY;
#pragma unroll
        for (int j = 0; j < TN; j++) {
            const int c = tx * 8 + j;
            float d2   = sqr + sqB[c] - 2.f * acc[i][j];
            float dist = sqrtf(fmaxf(d2, 1e-12f));
            if (tr == tB[c]) ap = fmaxf(ap, dist);
            else             an = fminf(an, dist);
        }
#pragma unroll
        for (int o = 8; o; o >>= 1) {
            ap = fmaxf(ap, __shfl_xor_sync(0xffffffffu, ap, o));
            an = fminf(an, __shfl_xor_sync(0xffffffffu, an, o));
        }
        if (tx == 0) {
            atomicMax(&g_ap[r0 + r], __float_as_uint(ap));
            atomicMin(&g_an[r0 + r], __float_as_uint(an));
        }
    }
}

// ---------------------------------------------------------------------------
// Kernel 2: fold 8192 rows into (loss, prec)
// ---------------------------------------------------------------------------
__global__ void final_kernel(float* __restrict__ out, int out_size)
{
    __shared__ float sl[256];
    __shared__ float sp[256];
    int tid = threadIdx.x;
    float loss = 0.f, prec = 0.f;
    for (int r = tid; r < NROWS; r += 256) {
        float ap = __uint_as_float(g_ap[r]);
        float an = __uint_as_float(g_an[r]);
        loss += fmaxf(ap - an + MARGIN, 0.f);
        prec += (an > ap) ? 1.f : 0.f;
    }
    sl[tid] = loss;
    sp[tid] = prec;
    __syncthreads();
    for (int s = 128; s; s >>= 1) {
        if (tid < s) { sl[tid] += sl[tid + s]; sp[tid] += sp[tid + s]; }
        __syncthreads();
    }
    if (tid == 0) {
        out[0] = sl[0] * (1.0f / NROWS);
        if (out_size > 1) out[1] = sp[0] * (1.0f / NROWS);
    }
}

// ---------------------------------------------------------------------------
extern "C" void kernel_launch(void* const* d_in, const int* in_sizes, int n_in,
                              void* d_out, int out_size)
{
    const float* x   = (const float*)d_in[0];
    const void*  tgt = d_in[1];
    float*       out = (float*)d_out;

    init_kernel<<<1, 1>>>();
    prep_kernel<<<NROWS / 8, 256>>>(x, (const int*)tgt);
    convert_kernel<<<NROWS / 256, 256>>>(tgt);

    dim3 grid(NROWS / BN, NROWS / BM);
    tile_kernel<<<grid, 256>>>(x);

    final_kernel<<<1, 256>>>(out, out_size);
}

// round 6
// speedup vs baseline: 1.9452x; 1.9452x over previous
#include <cuda_runtime.h>
#include <math.h>

#define NROWS 8192
#define DDIM  256
#define MARGIN 0.3f

#define BM 128
#define BN 128
#define BK 16
#define TM 8
#define TN 8
#define LDS_STRIDE 132   // 132 floats = 528 B; 528 % 16 == 0 -> aligned float4 rows

// Scratch (device globals: no allocation allowed in kernel_launch)
__device__ float        g_sq[NROWS];
__device__ unsigned int g_ap[NROWS];   // float bits, running max (dist >= 0)
__device__ unsigned int g_an[NROWS];   // float bits, running min
__device__ int          g_tgt[NROWS];  // canonicalized int32 targets
__device__ int          g_is32;        // 1 if targets buffer is int32, 0 if int64

// ---------------------------------------------------------------------------
__global__ void init_kernel() { g_is32 = 0; }

// row squared norms + reduction-array init + targets dtype detection
__global__ void prep_kernel(const float* __restrict__ x, const int* __restrict__ t32)
{
    int row  = blockIdx.x * 8 + (threadIdx.x >> 5);
    int lane = threadIdx.x & 31;
    const float* xr = x + (size_t)row * DDIM;
    float s = 0.f;
#pragma unroll
    for (int k = lane; k < DDIM; k += 32) {
        float v = xr[k];
        s = fmaf(v, v, s);
    }
#pragma unroll
    for (int o = 16; o; o >>= 1) s += __shfl_xor_sync(0xffffffffu, s, o);
    if (lane == 0) {
        g_sq[row] = s;
        g_ap[row] = 0u;           // 0.0f
        g_an[row] = 0x7f800000u;  // +inf
        if (row < 2048 && t32[2 * row + 1] != 0) atomicOr(&g_is32, 1);
    }
}

__global__ void convert_kernel(const void* __restrict__ tgt)
{
    int i = blockIdx.x * 256 + threadIdx.x;
    if (i < NROWS) {
        if (g_is32) g_tgt[i] = ((const int*)tgt)[i];
        else        g_tgt[i] = (int)((const long long*)tgt)[i];
    }
}

// ---------------------------------------------------------------------------
// Fused tile GEMM (X @ X^T), upper-triangular blocks only.
// Each off-diagonal tile feeds BOTH row-side and col-side max/min reductions.
// Ping-pong double-buffered smem: one __syncthreads per K-chunk.
// ---------------------------------------------------------------------------
__global__ __launch_bounds__(256, 2)
void tile_kernel(const float* __restrict__ x)
{
    const int bx = blockIdx.x;   // column block
    const int by = blockIdx.y;   // row block
    if (by > bx) return;         // symmetry: upper triangle only
    const bool diag = (bx == by);

    __shared__ float As[2][BK][LDS_STRIDE];
    __shared__ float Bs[2][BK][LDS_STRIDE];
    __shared__ float        sqA[BM];
    __shared__ float        sqB[BN];
    __shared__ int          tA[BM];
    __shared__ int          tB[BN];
    __shared__ unsigned int apC[BN];
    __shared__ unsigned int anC[BN];

    const int r0  = by * BM;
    const int c0  = bx * BN;
    const int tid = threadIdx.x;
    const int tx  = tid & 15;
    const int ty  = tid >> 4;

    if (tid < 128) {
        sqA[tid] = g_sq[r0 + tid];
        tA[tid]  = g_tgt[r0 + tid];
        apC[tid] = 0u;
        anC[tid] = 0x7f800000u;
    } else {
        int t = tid - 128;
        sqB[t] = g_sq[c0 + t];
        tB[t]  = g_tgt[c0 + t];
    }

    // Global-load mapping: each thread loads 2 float4 per tile (A and B each)
    const int lrow = tid >> 2;          // 0..63
    const int lcol = (tid & 3) * 4;     // 0,4,8,12

    const float* Abase = x + (size_t)(r0 + lrow) * DDIM + lcol;
    const float* Bbase = x + (size_t)(c0 + lrow) * DDIM + lcol;

    float acc[TM][TN];
#pragma unroll
    for (int i = 0; i < TM; i++)
#pragma unroll
        for (int j = 0; j < TN; j++) acc[i][j] = 0.f;

    // preload + store chunk 0 into buffer 0
    float4 a0 = *(const float4*)(Abase);
    float4 a1 = *(const float4*)(Abase + (size_t)64 * DDIM);
    float4 b0 = *(const float4*)(Bbase);
    float4 b1 = *(const float4*)(Bbase + (size_t)64 * DDIM);

    As[0][lcol + 0][lrow]      = a0.x;
    As[0][lcol + 1][lrow]      = a0.y;
    As[0][lcol + 2][lrow]      = a0.z;
    As[0][lcol + 3][lrow]      = a0.w;
    As[0][lcol + 0][lrow + 64] = a1.x;
    As[0][lcol + 1][lrow + 64] = a1.y;
    As[0][lcol + 2][lrow + 64] = a1.z;
    As[0][lcol + 3][lrow + 64] = a1.w;
    Bs[0][lcol + 0][lrow]      = b0.x;
    Bs[0][lcol + 1][lrow]      = b0.y;
    Bs[0][lcol + 2][lrow]      = b0.z;
    Bs[0][lcol + 3][lrow]      = b0.w;
    Bs[0][lcol + 0][lrow + 64] = b1.x;
    Bs[0][lcol + 1][lrow + 64] = b1.y;
    Bs[0][lcol + 2][lrow + 64] = b1.z;
    Bs[0][lcol + 3][lrow + 64] = b1.w;
    __syncthreads();

    const int NITER = DDIM / BK;
#pragma unroll 1
    for (int kk = 0; kk < NITER; ++kk) {
        const int cur = kk & 1;
        const int nxt = cur ^ 1;

        if (kk + 1 < NITER) {
            int off = (kk + 1) * BK;
            a0 = *(const float4*)(Abase + off);
            a1 = *(const float4*)(Abase + (size_t)64 * DDIM + off);
            b0 = *(const float4*)(Bbase + off);
            b1 = *(const float4*)(Bbase + (size_t)64 * DDIM + off);
        }

#pragma unroll
        for (int k = 0; k < BK; k++) {
            float4 ra0 = *(const float4*)&As[cur][k][ty * 8];
            float4 ra1 = *(const float4*)&As[cur][k][ty * 8 + 4];
            float4 rb0 = *(const float4*)&Bs[cur][k][tx * 8];
            float4 rb1 = *(const float4*)&Bs[cur][k][tx * 8 + 4];
            float ar[TM] = {ra0.x, ra0.y, ra0.z, ra0.w, ra1.x, ra1.y, ra1.z, ra1.w};
            float br[TN] = {rb0.x, rb0.y, rb0.z, rb0.w, rb1.x, rb1.y, rb1.z, rb1.w};
#pragma unroll
            for (int i = 0; i < TM; i++)
#pragma unroll
                for (int j = 0; j < TN; j++)
                    acc[i][j] = fmaf(ar[i], br[j], acc[i][j]);
        }

        if (kk + 1 < NITER) {
            As[nxt][lcol + 0][lrow]      = a0.x;
            As[nxt][lcol + 1][lrow]      = a0.y;
            As[nxt][lcol + 2][lrow]      = a0.z;
            As[nxt][lcol + 3][lrow]      = a0.w;
            As[nxt][lcol + 0][lrow + 64] = a1.x;
            As[nxt][lcol + 1][lrow + 64] = a1.y;
            As[nxt][lcol + 2][lrow + 64] = a1.z;
            As[nxt][lcol + 3][lrow + 64] = a1.w;
            Bs[nxt][lcol + 0][lrow]      = b0.x;
            Bs[nxt][lcol + 1][lrow]      = b0.y;
            Bs[nxt][lcol + 2][lrow]      = b0.z;
            Bs[nxt][lcol + 3][lrow]      = b0.w;
            Bs[nxt][lcol + 0][lrow + 64] = b1.x;
            Bs[nxt][lcol + 1][lrow + 64] = b1.y;
            Bs[nxt][lcol + 2][lrow + 64] = b1.z;
            Bs[nxt][lcol + 3][lrow + 64] = b1.w;
        }
        __syncthreads();
    }

    // ---- epilogue: dist once; update row-side AND col-side reductions ----
    float apc[TN], anc[TN];
#pragma unroll
    for (int j = 0; j < TN; j++) { apc[j] = 0.f; anc[j] = INFINITY; }

#pragma unroll
    for (int i = 0; i < TM; i++) {
        const int r    = ty * 8 + i;
        const float sqr = sqA[r];
        const int   tr  = tA[r];
        float ap = 0.f;
        float an = INFINITY;
#pragma unroll
        for (int j = 0; j < TN; j++) {
            const int c = tx * 8 + j;
            float d2   = sqr + sqB[c] - 2.f * acc[i][j];
            float dist = sqrtf(fmaxf(d2, 1e-12f));
            if (tr == tB[c]) { ap = fmaxf(ap, dist); apc[j] = fmaxf(apc[j], dist); }
            else             { an = fminf(an, dist); anc[j] = fminf(anc[j], dist); }
        }
        // row-side: reduce over the 16 tx lanes (xor stays within 16-lane half)
#pragma unroll
        for (int o = 8; o; o >>= 1) {
            ap = fmaxf(ap, __shfl_xor_sync(0xffffffffu, ap, o));
            an = fminf(an, __shfl_xor_sync(0xffffffffu, an, o));
        }
        if (tx == 0) {
            atomicMax(&g_ap[r0 + r], __float_as_uint(ap));
            atomicMin(&g_an[r0 + r], __float_as_uint(an));
        }
    }

    // col-side: smem atomics across the 16 ty groups, then 1 global atomic/col
    if (!diag) {
#pragma unroll
        for (int j = 0; j < TN; j++) {
            const int c = tx * 8 + j;
            if (apc[j] > 0.f)      atomicMax(&apC[c], __float_as_uint(apc[j]));
            if (anc[j] < INFINITY) atomicMin(&anC[c], __float_as_uint(anc[j]));
        }
        __syncthreads();
        if (tid < BN) {
            atomicMax(&g_ap[c0 + tid], apC[tid]);
            atomicMin(&g_an[c0 + tid], anC[tid]);
        }
    }
}

// ---------------------------------------------------------------------------
__global__ void final_kernel(float* __restrict__ out, int out_size)
{
    __shared__ float sl[256];
    __shared__ float sp[256];
    int tid = threadIdx.x;
    float loss = 0.f, prec = 0.f;
    for (int r = tid; r < NROWS; r += 256) {
        float ap = __uint_as_float(g_ap[r]);
        float an = __uint_as_float(g_an[r]);
        loss += fmaxf(ap - an + MARGIN, 0.f);
        prec += (an > ap) ? 1.f : 0.f;
    }
    sl[tid] = loss;
    sp[tid] = prec;
    __syncthreads();
    for (int s = 128; s; s >>= 1) {
        if (tid < s) { sl[tid] += sl[tid + s]; sp[tid] += sp[tid + s]; }
        __syncthreads();
    }
    if (tid == 0) {
        out[0] = sl[0] * (1.0f / NROWS);
        if (out_size > 1) out[1] = sp[0] * (1.0f / NROWS);
    }
}

// ---------------------------------------------------------------------------
extern "C" void kernel_launch(void* const* d_in, const int* in_sizes, int n_in,
                              void* d_out, int out_size)
{
    const float* x   = (const float*)d_in[0];
    const void*  tgt = d_in[1];
    float*       out = (float*)d_out;

    init_kernel<<<1, 1>>>();
    prep_kernel<<<NROWS / 8, 256>>>(x, (const int*)tgt);
    convert_kernel<<<NROWS / 256, 256>>>(tgt);

    dim3 grid(NROWS / BN, NROWS / BM);   // (64, 64); lower triangle exits early
    tile_kernel<<<grid, 256>>>(x);

    final_kernel<<<1, 256>>>(out, out_size);
}